// round 7
// baseline (speedup 1.0000x reference)
#include <cuda_runtime.h>
#include <cuda_bf16.h>
#include <math.h>
#include <stdint.h>

#define NN 100000
#define NE 1600000
#define NF 512
#define FD 128
#define NC 10
#define OUTC 12

// ================= PTX helpers (sm_80-compatible only) =================
__device__ __forceinline__ uint32_t s2u(const void* p) {
    uint32_t a;
    asm("{ .reg .u64 t; cvta.to.shared.u64 t, %1; cvt.u32.u64 %0, t; }"
        : "=r"(a) : "l"(p));
    return a;
}
__device__ __forceinline__ void cpa16(uint32_t dst, const void* src) {
    asm volatile("cp.async.cg.shared.global [%0], [%1], 16;" :: "r"(dst), "l"(src));
}
#define CP_COMMIT() asm volatile("cp.async.commit_group;" ::: "memory")
#define CP_WAIT1()  asm volatile("cp.async.wait_group 1;" ::: "memory")
#define CP_WAIT0()  asm volatile("cp.async.wait_group 0;" ::: "memory")

__device__ __forceinline__ void ldsm4(uint32_t* r, uint32_t addr) {
    asm volatile("ldmatrix.sync.aligned.m8n8.x4.shared.b16 {%0,%1,%2,%3}, [%4];"
                 : "=r"(r[0]), "=r"(r[1]), "=r"(r[2]), "=r"(r[3]) : "r"(addr));
}
__device__ __forceinline__ void mma16816(float* c, const uint32_t* a, const uint32_t* b) {
    asm volatile("mma.sync.aligned.m16n8k16.row.col.f32.bf16.bf16.f32 "
                 "{%0,%1,%2,%3}, {%4,%5,%6,%7}, {%8,%9}, {%0,%1,%2,%3};"
                 : "+f"(c[0]), "+f"(c[1]), "+f"(c[2]), "+f"(c[3])
                 : "r"(a[0]), "r"(a[1]), "r"(a[2]), "r"(a[3]), "r"(b[0]), "r"(b[1]));
}

// ================= scratch (device globals) =================
// Batched buffers: rows [0, NN) = good path, rows [NN, 2*NN) = bad path.
__device__ float g_Hg [(size_t)NN * FD];
__device__ float g_G  [(size_t)2 * NN * FD];
__device__ float g_EA2[(size_t)2 * NN * FD];
__device__ float g_E2 [(size_t)2 * NN * FD];
__device__ float g_T  [(size_t)NN * FD];
__device__ float g_C10[(size_t)NN * NC];
__device__ __nv_bfloat16 g_P1h[(size_t)2 * NN * FD];
__device__ __nv_bfloat16 g_P1l[(size_t)2 * NN * FD];
__device__ __nv_bfloat16 g_P2h[(size_t)2 * NN * FD];
__device__ __nv_bfloat16 g_P2l[(size_t)2 * NN * FD];
__device__ __nv_bfloat16 g_P3h[(size_t)NN * FD];
__device__ __nv_bfloat16 g_P3l[(size_t)NN * FD];
__device__ __nv_bfloat16 g_P4h[(size_t)NN * FD];
__device__ __nv_bfloat16 g_P4l[(size_t)NN * FD];
__device__ __nv_bfloat16 g_xh [(size_t)NN * NF];
__device__ __nv_bfloat16 g_xl [(size_t)NN * NF];
#define WOFF_W1 0
#define WOFF_W2 (128 * 512)
#define WOFF_W3 (WOFF_W2 + 128 * 128)
#define WOFF_M1 (WOFF_W3 + 128 * 128)
#define WOFF_M2 (WOFF_M1 + 128 * 128)
#define WOFF_WD (WOFF_M2 + 128 * 128)
#define WTOT    (WOFF_WD + 128 * 128)
__device__ __nv_bfloat16 g_Wh[WTOT];
__device__ __nv_bfloat16 g_Wl[WTOT];
__device__ int   g_cnt [2 * NN];
__device__ float g_dis [2 * NN];
__device__ float g_invd[2 * NN];
__device__ int   g_off [2 * (NN + 1)];
__device__ int   g_cur [2 * NN];
__device__ int   g_ssrc[2 * NE];
__device__ int   g_ssrcp[NE];
__device__ float g_sw  [2 * NE];

// ================= CSR build =================
__global__ void k_count(const int* __restrict__ dst, int* __restrict__ cnt) {
    int i = blockIdx.x * blockDim.x + threadIdx.x;
    if (i < NE) atomicAdd(&cnt[dst[i]], 1);
}

__global__ void k_deg(const int* __restrict__ cnt, float* __restrict__ dis,
                      float* __restrict__ invd) {
    int i = blockIdx.x * blockDim.x + threadIdx.x;
    if (i < NN) {
        float d = (float)(cnt[i] + 1);
        dis[i]  = rsqrtf(d);
        invd[i] = 1.0f / d;
    }
}

__global__ void k_scan(const int* __restrict__ cnt, int* __restrict__ off,
                       int* __restrict__ cur) {
    __shared__ int wsum[32];
    __shared__ int sbase;
    int t = threadIdx.x, w = t >> 5, l = t & 31;
    if (t == 0) sbase = 0;
    __syncthreads();
    for (int start = 0; start < NN; start += 1024) {
        int i = start + t;
        int v = (i < NN) ? cnt[i] : 0;
        int s = v;
        #pragma unroll
        for (int d = 1; d < 32; d <<= 1) {
            int o = __shfl_up_sync(0xffffffffu, s, d);
            if (l >= d) s += o;
        }
        if (l == 31) wsum[w] = s;
        __syncthreads();
        if (w == 0) {
            int ws = wsum[l];
            #pragma unroll
            for (int d = 1; d < 32; d <<= 1) {
                int o = __shfl_up_sync(0xffffffffu, ws, d);
                if (l >= d) ws += o;
            }
            wsum[l] = ws;
        }
        __syncthreads();
        int base = sbase + (w > 0 ? wsum[w - 1] : 0);
        int excl = base + s - v;
        if (i < NN) { off[i] = excl; cur[i] = excl; }
        int tot = wsum[31];
        __syncthreads();
        if (t == 0) sbase += tot;
        __syncthreads();
    }
    if (t == 0) off[NN] = sbase;
}

__global__ void k_place(const int* __restrict__ src, const int* __restrict__ dst,
                        const float* __restrict__ dis, int* __restrict__ cur,
                        int* __restrict__ ssrc, float* __restrict__ sw) {
    int e = blockIdx.x * blockDim.x + threadIdx.x;
    if (e < NE) {
        int s = src[e], d = dst[e];
        int p = atomicAdd(&cur[d], 1);
        ssrc[p] = s;
        sw[p]   = dis[s] * dis[d];
    }
}

__global__ void k_permsrc(const int* __restrict__ ssrc, const int* __restrict__ perm,
                          int* __restrict__ ssrcp) {
    int i = blockIdx.x * blockDim.x + threadIdx.x;
    if (i < NE) ssrcp[i] = perm[ssrc[i]];
}

// ================= splits =================
__global__ void k_splitx(const float* __restrict__ x, __nv_bfloat16* __restrict__ xh,
                         __nv_bfloat16* __restrict__ xl, int n) {
    int i = blockIdx.x * blockDim.x + threadIdx.x;
    if (i < n) {
        float v = x[i];
        __nv_bfloat16 h = __float2bfloat16(v);
        xh[i] = h;
        xl[i] = __float2bfloat16(v - __bfloat162float(h));
    }
}

__global__ void k_prepw(const float* __restrict__ W, __nv_bfloat16* __restrict__ Bh,
                        __nv_bfloat16* __restrict__ Bl, int K) {
    int i = blockIdx.x * blockDim.x + threadIdx.x;
    if (i < K * 128) {
        int n = i / K, k = i - n * K;
        float v = W[(size_t)k * 128 + n];
        __nv_bfloat16 h = __float2bfloat16(v);
        Bh[(size_t)n * K + k] = h;
        Bl[(size_t)n * K + k] = __float2bfloat16(v - __bfloat162float(h));
    }
}

// ================= mma.sync split-bf16 GEMM =================
#define STRIDE_B 80
#define ARR_SZ   (128 * STRIDE_B)
#define STAGE_SZ (4 * ARR_SZ)
#define SMEM_SZ  (2 * STAGE_SZ)

__device__ __forceinline__ void wmma_prefetch(
    uint32_t sbase, const __nv_bfloat16* Ah, const __nv_bfloat16* Al,
    const __nv_bfloat16* Bh, const __nv_bfloat16* Bl,
    int m0, int M, int K, int k0, int tid)
{
    #pragma unroll
    for (int p = 0; p < 2; p++) {
        int idx = tid + p * 256;
        int row = idx >> 2, cg = idx & 3;
        int gr = m0 + row; if (gr >= M) gr = M - 1;
        size_t aoff = (size_t)gr * K + k0 + cg * 8;
        size_t boff = (size_t)row * K + k0 + cg * 8;
        uint32_t so = row * STRIDE_B + cg * 16;
        cpa16(sbase + 0 * ARR_SZ + so, Ah + aoff);
        cpa16(sbase + 1 * ARR_SZ + so, Al + aoff);
        cpa16(sbase + 2 * ARR_SZ + so, Bh + boff);
        cpa16(sbase + 3 * ARR_SZ + so, Bl + boff);
    }
}

__global__ void __launch_bounds__(256, 1) k_wmma(
    const __nv_bfloat16* __restrict__ Ahi, const __nv_bfloat16* __restrict__ Alo,
    const __nv_bfloat16* __restrict__ Bhi, const __nv_bfloat16* __restrict__ Blo,
    const float* __restrict__ bias, int dorelu,
    float* __restrict__ Cf, __nv_bfloat16* __restrict__ Chi,
    __nv_bfloat16* __restrict__ Clo, int M, int K)
{
    extern __shared__ char smem[];
    const uint32_t sb = s2u(smem);
    const int tid  = threadIdx.x;
    const int lane = tid & 31, w = tid >> 5;
    const int wm0 = (w >> 1) * 32, wn0 = (w & 1) * 64;
    const int m0  = blockIdx.x * 128;

    float c[2][8][4];
    #pragma unroll
    for (int i = 0; i < 2; i++)
        #pragma unroll
        for (int j = 0; j < 8; j++)
            #pragma unroll
            for (int q = 0; q < 4; q++) c[i][j][q] = 0.f;

    const uint32_t aoffs = (uint32_t)((wm0 + (lane & 15)) * STRIDE_B + (lane >> 4) * 16);
    const uint32_t boffs = (uint32_t)((wn0 + ((lane >> 4) & 1) * 8 + (lane & 7)) * STRIDE_B
                                      + ((lane >> 3) & 1) * 16);

    const int nch = K >> 5;
    wmma_prefetch(sb, Ahi, Alo, Bhi, Blo, m0, M, K, 0, tid);
    CP_COMMIT();

    for (int ch = 0; ch < nch; ch++) {
        if (ch + 1 < nch) {
            wmma_prefetch(sb + ((ch + 1) & 1) * STAGE_SZ, Ahi, Alo, Bhi, Blo,
                          m0, M, K, (ch + 1) << 5, tid);
            CP_COMMIT();
            CP_WAIT1();
        } else {
            CP_WAIT0();
        }
        __syncthreads();

        const uint32_t st = sb + (ch & 1) * STAGE_SZ;
        #pragma unroll
        for (int kk = 0; kk < 2; kk++) {
            const uint32_t kb = kk * 32;
            uint32_t ah[2][4], al[2][4], bh[4][4], bl[4][4];
            #pragma unroll
            for (int mt = 0; mt < 2; mt++) {
                uint32_t ao = st + aoffs + mt * (16 * STRIDE_B) + kb;
                ldsm4(ah[mt], ao + 0 * ARR_SZ);
                ldsm4(al[mt], ao + 1 * ARR_SZ);
            }
            #pragma unroll
            for (int np = 0; np < 4; np++) {
                uint32_t bo = st + boffs + np * (16 * STRIDE_B) + kb;
                ldsm4(bh[np], bo + 2 * ARR_SZ);
                ldsm4(bl[np], bo + 3 * ARR_SZ);
            }
            #pragma unroll
            for (int mt = 0; mt < 2; mt++)
                #pragma unroll
                for (int nt = 0; nt < 8; nt++) {
                    float* cc = c[mt][nt];
                    const uint32_t* ph = &bh[nt >> 1][(nt & 1) * 2];
                    const uint32_t* pl = &bl[nt >> 1][(nt & 1) * 2];
                    mma16816(cc, ah[mt], ph);
                    mma16816(cc, ah[mt], pl);
                    mma16816(cc, al[mt], ph);
                }
        }
        __syncthreads();
    }

    #pragma unroll
    for (int mt = 0; mt < 2; mt++) {
        #pragma unroll
        for (int part = 0; part < 2; part++) {
            int gr = m0 + wm0 + mt * 16 + (lane >> 2) + part * 8;
            if (gr >= M) continue;
            #pragma unroll
            for (int nt = 0; nt < 8; nt++) {
                int gcol = wn0 + nt * 8 + (lane & 3) * 2;
                float v0 = c[mt][nt][part * 2 + 0];
                float v1 = c[mt][nt][part * 2 + 1];
                if (bias) { v0 += bias[gcol]; v1 += bias[gcol + 1]; }
                if (dorelu) { v0 = fmaxf(v0, 0.f); v1 = fmaxf(v1, 0.f); }
                if (Cf)
                    *(float2*)(Cf + (size_t)gr * FD + gcol) = make_float2(v0, v1);
                if (Chi) {
                    __nv_bfloat16 h0 = __float2bfloat16(v0);
                    __nv_bfloat16 h1 = __float2bfloat16(v1);
                    __nv_bfloat162 hp = __halves2bfloat162(h0, h1);
                    __nv_bfloat162 lp = __halves2bfloat162(
                        __float2bfloat16(v0 - __bfloat162float(h0)),
                        __float2bfloat16(v1 - __bfloat162float(h1)));
                    *(uint32_t*)(Chi + (size_t)gr * FD + gcol) = *(uint32_t*)&hp;
                    *(uint32_t*)(Clo + (size_t)gr * FD + gcol) = *(uint32_t*)&lp;
                }
            }
        }
    }
}

// ======== batched gather aggregation: good part + bad part, one launch ========
// Warp w handles output row w in [0, 2*NN). part = w >= NN; node = w - part*NN.
// Part A gathers from h rows ssrcA[i]; part B from (h + hShiftB) rows ssrcB[i].
// Self row: part A -> node; part B -> (selfB ? selfB[node] : node) + hShiftB rows.
__global__ void k_agg2(const float* __restrict__ h, size_t hShiftB,
                       const int* __restrict__ ssrcA, const int* __restrict__ ssrcB,
                       const int* __restrict__ selfB,
                       const int* __restrict__ off, const float* __restrict__ sw,
                       const float* __restrict__ invd, const float* __restrict__ bias,
                       float* __restrict__ outf, __nv_bfloat16* __restrict__ outhi,
                       __nv_bfloat16* __restrict__ outlo, int dorelu)
{
    const unsigned FULL = 0xffffffffu;
    int w = (blockIdx.x * blockDim.x + threadIdx.x) >> 5;
    int lane = threadIdx.x & 31;
    if (w >= 2 * NN) return;
    int part = (w >= NN);
    int node = w - part * NN;
    const int* ssrc = part ? ssrcB : ssrcA;
    const float* hb = h + (part ? hShiftB : 0);

    int s = off[node], e = off[node + 1];
    float4 acc = make_float4(0.f, 0.f, 0.f, 0.f);
    int i = s;
    for (; i + 32 <= e; i += 32) {
        int   idx = ssrc[i + lane];
        float wv  = sw[i + lane];
        #pragma unroll 8
        for (int j = 0; j < 32; j++) {
            int   sj = __shfl_sync(FULL, idx, j);
            float wj = __shfl_sync(FULL, wv, j);
            float4 v = *(const float4*)(hb + (size_t)sj * FD + lane * 4);
            acc.x = fmaf(wj, v.x, acc.x);
            acc.y = fmaf(wj, v.y, acc.y);
            acc.z = fmaf(wj, v.z, acc.z);
            acc.w = fmaf(wj, v.w, acc.w);
        }
    }
    if (i < e) {
        int m = e - i;
        int   idx = (lane < m) ? ssrc[i + lane] : 0;
        float wv  = (lane < m) ? sw[i + lane] : 0.f;
        for (int j = 0; j < m; j++) {
            int   sj = __shfl_sync(FULL, idx, j);
            float wj = __shfl_sync(FULL, wv, j);
            float4 v = *(const float4*)(hb + (size_t)sj * FD + lane * 4);
            acc.x = fmaf(wj, v.x, acc.x);
            acc.y = fmaf(wj, v.y, acc.y);
            acc.z = fmaf(wj, v.z, acc.z);
            acc.w = fmaf(wj, v.w, acc.w);
        }
    }
    int self = part ? (selfB ? selfB[node] : node) : node;
    float  id = invd[node];
    float4 hv = *(const float4*)(hb + (size_t)self * FD + lane * 4);
    float4 b  = *(const float4*)(bias + lane * 4);
    acc.x = fmaf(id, hv.x, acc.x) + b.x;
    acc.y = fmaf(id, hv.y, acc.y) + b.y;
    acc.z = fmaf(id, hv.z, acc.z) + b.z;
    acc.w = fmaf(id, hv.w, acc.w) + b.w;
    if (dorelu) {
        acc.x = fmaxf(acc.x, 0.f); acc.y = fmaxf(acc.y, 0.f);
        acc.z = fmaxf(acc.z, 0.f); acc.w = fmaxf(acc.w, 0.f);
    }
    if (outf)
        *(float4*)(outf + (size_t)w * FD + lane * 4) = acc;
    if (outhi) {
        float vv[4] = {acc.x, acc.y, acc.z, acc.w};
        uint32_t hw[2], lw[2];
        #pragma unroll
        for (int q = 0; q < 2; q++) {
            __nv_bfloat16 ha = __float2bfloat16(vv[2 * q]);
            __nv_bfloat16 hb2 = __float2bfloat16(vv[2 * q + 1]);
            __nv_bfloat162 hp = __halves2bfloat162(ha, hb2);
            __nv_bfloat162 lp = __halves2bfloat162(
                __float2bfloat16(vv[2 * q] - __bfloat162float(ha)),
                __float2bfloat16(vv[2 * q + 1] - __bfloat162float(hb2)));
            hw[q] = *(uint32_t*)&hp;
            lw[q] = *(uint32_t*)&lp;
        }
        *(uint2*)(outhi + (size_t)w * FD + lane * 4) = make_uint2(hw[0], hw[1]);
        *(uint2*)(outlo + (size_t)w * FD + lane * 4) = make_uint2(lw[0], lw[1]);
    }
}

// ================= classifier GEMM (128 -> 10) =================
__global__ void k_gemm10(const float* __restrict__ A, const float* __restrict__ W,
                         float* __restrict__ C)
{
    __shared__ float w[FD * NC];
    for (int i = threadIdx.x; i < FD * NC; i += blockDim.x) w[i] = W[i];
    __syncthreads();
    int r = blockIdx.x * blockDim.x + threadIdx.x;
    if (r >= NN) return;
    float acc[NC];
    #pragma unroll
    for (int j = 0; j < NC; j++) acc[j] = 0.f;
    const float4* ap = (const float4*)(A + (size_t)r * FD);
    #pragma unroll 8
    for (int k4 = 0; k4 < 32; k4++) {
        float4 v = ap[k4];
        int k = k4 * 4;
        #pragma unroll
        for (int j = 0; j < NC; j++) {
            acc[j] = fmaf(v.x, w[(k + 0) * NC + j], acc[j]);
            acc[j] = fmaf(v.y, w[(k + 1) * NC + j], acc[j]);
            acc[j] = fmaf(v.z, w[(k + 2) * NC + j], acc[j]);
            acc[j] = fmaf(v.w, w[(k + 3) * NC + j], acc[j]);
        }
    }
    #pragma unroll
    for (int j = 0; j < NC; j++) C[(size_t)r * NC + j] = acc[j];
}

__global__ void k_agg10(const float* __restrict__ h, const int* __restrict__ off,
                        const int* __restrict__ ssrc, const float* __restrict__ sw,
                        const float* __restrict__ invd, const float* __restrict__ bc,
                        float* __restrict__ out)
{
    const unsigned FULL = 0xffffffffu;
    int node = (blockIdx.x * blockDim.x + threadIdx.x) >> 5;
    int lane = threadIdx.x & 31;
    if (node >= NN) return;
    int s = off[node], e = off[node + 1];
    float acc = 0.f;
    int i = s;
    for (; i + 32 <= e; i += 32) {
        int   idx = ssrc[i + lane];
        float wv  = sw[i + lane];
        #pragma unroll 8
        for (int j = 0; j < 32; j++) {
            int   sj = __shfl_sync(FULL, idx, j);
            float wj = __shfl_sync(FULL, wv, j);
            if (lane < NC)
                acc = fmaf(wj, h[(size_t)sj * NC + lane], acc);
        }
    }
    if (i < e) {
        int m = e - i;
        int   idx = (lane < m) ? ssrc[i + lane] : 0;
        float wv  = (lane < m) ? sw[i + lane] : 0.f;
        for (int j = 0; j < m; j++) {
            int   sj = __shfl_sync(FULL, idx, j);
            float wj = __shfl_sync(FULL, wv, j);
            if (lane < NC)
                acc = fmaf(wj, h[(size_t)sj * NC + lane], acc);
        }
    }
    if (lane < NC) {
        acc = fmaf(invd[node], h[(size_t)node * NC + lane], acc) + bc[lane];
        out[(size_t)node * OUTC + lane] = acc;
    }
}

// ========== combined score: cols 10 (good) and 11 (bad), one launch ==========
__global__ void k_score2(const float* __restrict__ t, const float* __restrict__ e2,
                         float* __restrict__ out)
{
    int w = (blockIdx.x * blockDim.x + threadIdx.x) >> 5;
    int lane = threadIdx.x & 31;
    if (w >= 2 * NN) return;
    int part = (w >= NN);
    int row  = w - part * NN;
    float4 a = *(const float4*)(t  + (size_t)row * FD + lane * 4);
    float4 b = *(const float4*)(e2 + (size_t)w   * FD + lane * 4);
    float s = a.x * b.x + a.y * b.y + a.z * b.z + a.w * b.w;
    #pragma unroll
    for (int d = 16; d > 0; d >>= 1) s += __shfl_xor_sync(0xffffffffu, s, d);
    if (lane == 0)
        out[(size_t)row * OUTC + 10 + part] = 1.0f / (1.0f + expf(-s));
}

// ================= host =================
extern "C" void kernel_launch(void* const* d_in, const int* in_sizes, int n_in,
                              void* d_out, int out_size)
{
    const float* x    = (const float*)d_in[0];
    const int*   ei   = (const int*)  d_in[1];
    const int*   eh   = (const int*)  d_in[2];
    const int*   perm = (const int*)  d_in[4];
    const float* W1   = (const float*)d_in[5];
    const float* b1   = (const float*)d_in[6];
    const float* W2   = (const float*)d_in[7];
    const float* b2   = (const float*)d_in[8];
    const float* W3   = (const float*)d_in[9];
    const float* b3   = (const float*)d_in[10];
    const float* M1   = (const float*)d_in[11];
    const float* mb1  = (const float*)d_in[12];
    const float* M2   = (const float*)d_in[13];
    const float* mb2  = (const float*)d_in[14];
    const float* Wc   = (const float*)d_in[15];
    const float* bc   = (const float*)d_in[16];
    const float* Wd   = (const float*)d_in[17];
    float* out = (float*)d_out;

    float *Hg, *G, *EA2, *E2, *T, *C10, *dis, *invd, *sw;
    __nv_bfloat16 *P1h, *P1l, *P2h, *P2l, *P3h, *P3l, *P4h, *P4l, *xh, *xl, *Wh, *Wl;
    int *cnt, *off, *cur, *ssrc, *ssrcp;
    cudaGetSymbolAddress((void**)&Hg,   g_Hg);
    cudaGetSymbolAddress((void**)&G,    g_G);
    cudaGetSymbolAddress((void**)&EA2,  g_EA2);
    cudaGetSymbolAddress((void**)&E2,   g_E2);
    cudaGetSymbolAddress((void**)&T,    g_T);
    cudaGetSymbolAddress((void**)&C10,  g_C10);
    cudaGetSymbolAddress((void**)&P1h,  g_P1h);
    cudaGetSymbolAddress((void**)&P1l,  g_P1l);
    cudaGetSymbolAddress((void**)&P2h,  g_P2h);
    cudaGetSymbolAddress((void**)&P2l,  g_P2l);
    cudaGetSymbolAddress((void**)&P3h,  g_P3h);
    cudaGetSymbolAddress((void**)&P3l,  g_P3l);
    cudaGetSymbolAddress((void**)&P4h,  g_P4h);
    cudaGetSymbolAddress((void**)&P4l,  g_P4l);
    cudaGetSymbolAddress((void**)&xh,   g_xh);
    cudaGetSymbolAddress((void**)&xl,   g_xl);
    cudaGetSymbolAddress((void**)&Wh,   g_Wh);
    cudaGetSymbolAddress((void**)&Wl,   g_Wl);
    cudaGetSymbolAddress((void**)&cnt,  g_cnt);
    cudaGetSymbolAddress((void**)&dis,  g_dis);
    cudaGetSymbolAddress((void**)&invd, g_invd);
    cudaGetSymbolAddress((void**)&off,  g_off);
    cudaGetSymbolAddress((void**)&cur,  g_cur);
    cudaGetSymbolAddress((void**)&ssrc, g_ssrc);
    cudaGetSymbolAddress((void**)&ssrcp,g_ssrcp);
    cudaGetSymbolAddress((void**)&sw,   g_sw);

    cudaFuncSetAttribute(k_wmma, cudaFuncAttributeMaxDynamicSharedMemorySize, SMEM_SZ);

    const int TE  = 256;
    const int GE  = (NE + TE - 1) / TE;
    const int GN  = (NN + TE - 1) / TE;
    const int GW  = (NN * 32 + TE - 1) / TE;
    const int GW2 = (2 * NN * 32 + TE - 1) / TE;
    const int GM  = (NN + 127) / 128;
    const int GM2 = (2 * NN + 127) / 128;

    // ---- CSR build (both graphs) ----
    cudaMemsetAsync(cnt, 0, sizeof(int) * 2 * NN);
    k_count<<<GE, TE>>>(ei + NE, cnt);
    k_count<<<GE, TE>>>(eh + NE, cnt + NN);
    k_deg<<<GN, TE>>>(cnt,      dis,      invd);
    k_deg<<<GN, TE>>>(cnt + NN, dis + NN, invd + NN);
    k_scan<<<1, 1024>>>(cnt,      off,            cur);
    k_scan<<<1, 1024>>>(cnt + NN, off + (NN + 1), cur + NN);
    k_place<<<GE, TE>>>(ei, ei + NE, dis,      cur,      ssrc,      sw);
    k_place<<<GE, TE>>>(eh, eh + NE, dis + NN, cur + NN, ssrc + NE, sw + NE);
    k_permsrc<<<GE, TE>>>(ssrc, perm, ssrcp);

    // ---- splits / weight prep ----
    k_splitx<<<(NN * NF + 255) / 256, 256>>>(x, xh, xl, NN * NF);
    k_prepw<<<(512 * 128 + 255) / 256, 256>>>(W1, Wh + WOFF_W1, Wl + WOFF_W1, 512);
    k_prepw<<<(128 * 128 + 255) / 256, 256>>>(W2, Wh + WOFF_W2, Wl + WOFF_W2, 128);
    k_prepw<<<(128 * 128 + 255) / 256, 256>>>(W3, Wh + WOFF_W3, Wl + WOFF_W3, 128);
    k_prepw<<<(128 * 128 + 255) / 256, 256>>>(M1, Wh + WOFF_M1, Wl + WOFF_M1, 128);
    k_prepw<<<(128 * 128 + 255) / 256, 256>>>(M2, Wh + WOFF_M2, Wl + WOFF_M2, 128);
    k_prepw<<<(128 * 128 + 255) / 256, 256>>>(Wd, Wh + WOFF_WD, Wl + WOFF_WD, 128);

    // ---- Hg = x @ W1 (good only; bad layer1 = Hg[perm]) ----
    k_wmma<<<GM, 256, SMEM_SZ>>>(xh, xl, Wh + WOFF_W1, Wl + WOFF_W1,
                                 nullptr, 0, Hg, nullptr, nullptr, NN, 512);

    // ---- batched layer1 agg: good (ssrc) + bad (ssrcp, self=perm), both from Hg ----
    k_agg2<<<GW2, TE>>>(Hg, 0, ssrc, ssrcp, perm,
                        off, sw, invd, b1, nullptr, P1h, P1l, 1);

    // ---- batched layer2: GEMM W2 (M=2NN) + agg ----
    k_wmma<<<GM2, 256, SMEM_SZ>>>(P1h, P1l, Wh + WOFF_W2, Wl + WOFF_W2,
                                  nullptr, 0, G, nullptr, nullptr, 2 * NN, 128);
    k_agg2<<<GW2, TE>>>(G, (size_t)NN * FD, ssrc, ssrc, nullptr,
                        off, sw, invd, b2, EA2, P2h, P2l, 1);

    // ---- batched encoder2: GEMM W3 (M=2NN) + hop agg ----
    k_wmma<<<GM2, 256, SMEM_SZ>>>(P2h, P2l, Wh + WOFF_W3, Wl + WOFF_W3,
                                  nullptr, 0, G, nullptr, nullptr, 2 * NN, 128);
    k_agg2<<<GW2, TE>>>(G, (size_t)NN * FD, ssrc + NE, ssrc + NE, nullptr,
                        off + (NN + 1), sw + NE, invd + NN, b3,
                        E2, nullptr, nullptr, 0);

    // ---- encoder3 MLP + discriminator T (good P2 rows only) ----
    k_wmma<<<GM, 256, SMEM_SZ>>>(P2h, P2l, Wh + WOFF_M1, Wl + WOFF_M1,
                                 mb1, 1, nullptr, P3h, P3l, NN, 128);
    k_wmma<<<GM, 256, SMEM_SZ>>>(P3h, P3l, Wh + WOFF_M2, Wl + WOFF_M2,
                                 mb2, 0, nullptr, P4h, P4l, NN, 128);
    k_wmma<<<GM, 256, SMEM_SZ>>>(P4h, P4l, Wh + WOFF_WD, Wl + WOFF_WD,
                                 nullptr, 0, T, nullptr, nullptr, NN, 128);

    // ---- both scores, one launch ----
    k_score2<<<GW2, TE>>>(T, E2, out);

    // ---- classifier GCN -> out cols 0..9 (good EA rows) ----
    k_gemm10<<<GN, TE>>>(EA2, Wc, C10);
    k_agg10<<<GW, TE>>>(C10, off, ssrc, sw, invd, bc, out);
}

// round 9
// speedup vs baseline: 1.1714x; 1.1714x over previous
#include <cuda_runtime.h>
#include <cuda_bf16.h>
#include <math.h>
#include <stdint.h>

#define NN 100000
#define NE 1600000
#define NF 512
#define FD 128
#define NC 10
#define OUTC 12

// ================= PTX helpers (sm_80-compatible only) =================
__device__ __forceinline__ uint32_t s2u(const void* p) {
    uint32_t a;
    asm("{ .reg .u64 t; cvta.to.shared.u64 t, %1; cvt.u32.u64 %0, t; }"
        : "=r"(a) : "l"(p));
    return a;
}
__device__ __forceinline__ void cpa16(uint32_t dst, const void* src) {
    asm volatile("cp.async.cg.shared.global [%0], [%1], 16;" :: "r"(dst), "l"(src));
}
#define CP_COMMIT() asm volatile("cp.async.commit_group;" ::: "memory")
#define CP_WAIT1()  asm volatile("cp.async.wait_group 1;" ::: "memory")
#define CP_WAIT0()  asm volatile("cp.async.wait_group 0;" ::: "memory")

__device__ __forceinline__ void ldsm4(uint32_t* r, uint32_t addr) {
    asm volatile("ldmatrix.sync.aligned.m8n8.x4.shared.b16 {%0,%1,%2,%3}, [%4];"
                 : "=r"(r[0]), "=r"(r[1]), "=r"(r[2]), "=r"(r[3]) : "r"(addr));
}
__device__ __forceinline__ void mma16816(float* c, const uint32_t* a, const uint32_t* b) {
    asm volatile("mma.sync.aligned.m16n8k16.row.col.f32.bf16.bf16.f32 "
                 "{%0,%1,%2,%3}, {%4,%5,%6,%7}, {%8,%9}, {%0,%1,%2,%3};"
                 : "+f"(c[0]), "+f"(c[1]), "+f"(c[2]), "+f"(c[3])
                 : "r"(a[0]), "r"(a[1]), "r"(a[2]), "r"(a[3]), "r"(b[0]), "r"(b[1]));
}

// ================= scratch (device globals) =================
__device__ float g_Hg [(size_t)NN * FD];
__device__ float g_G  [(size_t)NN * FD];
__device__ float g_EAf[(size_t)NN * FD];
__device__ float g_T  [(size_t)NN * FD];
__device__ float g_C10[(size_t)NN * NC];
__device__ __nv_bfloat16 g_P1h[(size_t)NN * FD];
__device__ __nv_bfloat16 g_P1l[(size_t)NN * FD];
__device__ __nv_bfloat16 g_P2h[(size_t)NN * FD];
__device__ __nv_bfloat16 g_P2l[(size_t)NN * FD];
__device__ __nv_bfloat16 g_P3h[(size_t)NN * FD];
__device__ __nv_bfloat16 g_P3l[(size_t)NN * FD];
__device__ __nv_bfloat16 g_P4h[(size_t)NN * FD];
__device__ __nv_bfloat16 g_P4l[(size_t)NN * FD];
__device__ __nv_bfloat16 g_xh [(size_t)NN * NF];
__device__ __nv_bfloat16 g_xl [(size_t)NN * NF];
#define WOFF_W1 0
#define WOFF_W2 (128 * 512)
#define WOFF_W3 (WOFF_W2 + 128 * 128)
#define WOFF_M1 (WOFF_W3 + 128 * 128)
#define WOFF_M2 (WOFF_M1 + 128 * 128)
#define WOFF_WD (WOFF_M2 + 128 * 128)
#define WTOT    (WOFF_WD + 128 * 128)
__device__ __nv_bfloat16 g_Wh[WTOT];
__device__ __nv_bfloat16 g_Wl[WTOT];
__device__ int   g_cnt [2 * NN];
__device__ float g_dis [2 * NN];
__device__ float g_invd[2 * NN];
__device__ int   g_off [2 * (NN + 1)];
__device__ int   g_cur [2 * NN];
__device__ int   g_btot[2 * 128];
__device__ int   g_ssrc[2 * NE];
__device__ int   g_ssrcp[NE];
__device__ float g_sw  [2 * NE];

// ================= CSR build =================
__global__ void k_count(const int* __restrict__ dst, int* __restrict__ cnt) {
    int i = blockIdx.x * blockDim.x + threadIdx.x;
    if (i < NE) atomicAdd(&cnt[dst[i]], 1);
}

__global__ void k_deg(const int* __restrict__ cnt, float* __restrict__ dis,
                      float* __restrict__ invd) {
    int i = blockIdx.x * blockDim.x + threadIdx.x;
    if (i < NN) {
        float d = (float)(cnt[i] + 1);
        dis[i]  = rsqrtf(d);
        invd[i] = 1.0f / d;
    }
}

// ---- multi-block scan: blk-local excl scan + block totals ----
#define SCB 1024
__global__ void k_scan_blk(const int* __restrict__ cnt, int* __restrict__ off,
                           int* __restrict__ btot, int n) {
    __shared__ int ws[32];
    const unsigned FULL = 0xffffffffu;
    int t = threadIdx.x, w = t >> 5, l = t & 31;
    int i = blockIdx.x * SCB + t;
    int v = (i < n) ? cnt[i] : 0;
    int s = v;
    #pragma unroll
    for (int d = 1; d < 32; d <<= 1) {
        int o = __shfl_up_sync(FULL, s, d);
        if (l >= d) s += o;
    }
    if (l == 31) ws[w] = s;
    __syncthreads();
    if (w == 0) {
        int x2 = ws[l];
        #pragma unroll
        for (int d = 1; d < 32; d <<= 1) {
            int o = __shfl_up_sync(FULL, x2, d);
            if (l >= d) x2 += o;
        }
        ws[l] = x2;
    }
    __syncthreads();
    int incl = s + (w > 0 ? ws[w - 1] : 0);
    if (i < n) off[i] = incl - v;
    if (t == SCB - 1) btot[blockIdx.x] = incl;
}

// exclusive-scan block totals (nb <= 128), write grand total to *offN
__global__ void k_scan_tot(int* __restrict__ btot, int nb, int* __restrict__ offN) {
    __shared__ int sh[128];
    int t = threadIdx.x;
    int v = (t < nb) ? btot[t] : 0;
    sh[t] = v;
    __syncthreads();
    #pragma unroll
    for (int d = 1; d < 128; d <<= 1) {
        int o = (t >= d) ? sh[t - d] : 0;
        __syncthreads();
        sh[t] += o;
        __syncthreads();
    }
    if (t < nb) btot[t] = sh[t] - v;
    if (t == 127) *offN = sh[127];
}

__global__ void k_scan_add(int* __restrict__ off, const int* __restrict__ btot,
                           int* __restrict__ cur, int n) {
    int i = blockIdx.x * blockDim.x + threadIdx.x;
    if (i < n) {
        int e = off[i] + btot[i >> 10];
        off[i] = e;
        cur[i] = e;
    }
}

__global__ void k_place(const int* __restrict__ src, const int* __restrict__ dst,
                        const float* __restrict__ dis, int* __restrict__ cur,
                        int* __restrict__ ssrc, float* __restrict__ sw) {
    int e = blockIdx.x * blockDim.x + threadIdx.x;
    if (e < NE) {
        int s = src[e], d = dst[e];
        int p = atomicAdd(&cur[d], 1);
        ssrc[p] = s;
        sw[p]   = dis[s] * dis[d];
    }
}

__global__ void k_permsrc(const int* __restrict__ ssrc, const int* __restrict__ perm,
                          int* __restrict__ ssrcp) {
    int i = blockIdx.x * blockDim.x + threadIdx.x;
    if (i < NE) ssrcp[i] = perm[ssrc[i]];
}

// ================= splits =================
__global__ void k_splitx(const float* __restrict__ x, __nv_bfloat16* __restrict__ xh,
                         __nv_bfloat16* __restrict__ xl, int n) {
    int i = blockIdx.x * blockDim.x + threadIdx.x;
    if (i < n) {
        float v = x[i];
        __nv_bfloat16 h = __float2bfloat16(v);
        xh[i] = h;
        xl[i] = __float2bfloat16(v - __bfloat162float(h));
    }
}

__global__ void k_prepw(const float* __restrict__ W, __nv_bfloat16* __restrict__ Bh,
                        __nv_bfloat16* __restrict__ Bl, int K) {
    int i = blockIdx.x * blockDim.x + threadIdx.x;
    if (i < K * 128) {
        int n = i / K, k = i - n * K;
        float v = W[(size_t)k * 128 + n];
        __nv_bfloat16 h = __float2bfloat16(v);
        Bh[(size_t)n * K + k] = h;
        Bl[(size_t)n * K + k] = __float2bfloat16(v - __bfloat162float(h));
    }
}

// ================= mma.sync split-bf16 GEMM =================
#define STRIDE_B 80
#define ARR_SZ   (128 * STRIDE_B)
#define STAGE_SZ (4 * ARR_SZ)
#define SMEM_SZ  (2 * STAGE_SZ)

__device__ __forceinline__ void wmma_prefetch(
    uint32_t sbase, const __nv_bfloat16* Ah, const __nv_bfloat16* Al,
    const __nv_bfloat16* Bh, const __nv_bfloat16* Bl,
    int m0, int M, int K, int k0, int tid)
{
    #pragma unroll
    for (int p = 0; p < 2; p++) {
        int idx = tid + p * 256;
        int row = idx >> 2, cg = idx & 3;
        int gr = m0 + row; if (gr >= M) gr = M - 1;
        size_t aoff = (size_t)gr * K + k0 + cg * 8;
        size_t boff = (size_t)row * K + k0 + cg * 8;
        uint32_t so = row * STRIDE_B + cg * 16;
        cpa16(sbase + 0 * ARR_SZ + so, Ah + aoff);
        cpa16(sbase + 1 * ARR_SZ + so, Al + aoff);
        cpa16(sbase + 2 * ARR_SZ + so, Bh + boff);
        cpa16(sbase + 3 * ARR_SZ + so, Bl + boff);
    }
}

__global__ void __launch_bounds__(256, 1) k_wmma(
    const __nv_bfloat16* __restrict__ Ahi, const __nv_bfloat16* __restrict__ Alo,
    const __nv_bfloat16* __restrict__ Bhi, const __nv_bfloat16* __restrict__ Blo,
    const float* __restrict__ bias, int dorelu,
    float* __restrict__ Cf, __nv_bfloat16* __restrict__ Chi,
    __nv_bfloat16* __restrict__ Clo, int M, int K)
{
    extern __shared__ char smem[];
    const uint32_t sb = s2u(smem);
    const int tid  = threadIdx.x;
    const int lane = tid & 31, w = tid >> 5;
    const int wm0 = (w >> 1) * 32, wn0 = (w & 1) * 64;
    const int m0  = blockIdx.x * 128;

    float c[2][8][4];
    #pragma unroll
    for (int i = 0; i < 2; i++)
        #pragma unroll
        for (int j = 0; j < 8; j++)
            #pragma unroll
            for (int q = 0; q < 4; q++) c[i][j][q] = 0.f;

    const uint32_t aoffs = (uint32_t)((wm0 + (lane & 15)) * STRIDE_B + (lane >> 4) * 16);
    const uint32_t boffs = (uint32_t)((wn0 + ((lane >> 4) & 1) * 8 + (lane & 7)) * STRIDE_B
                                      + ((lane >> 3) & 1) * 16);

    const int nch = K >> 5;
    wmma_prefetch(sb, Ahi, Alo, Bhi, Blo, m0, M, K, 0, tid);
    CP_COMMIT();

    for (int ch = 0; ch < nch; ch++) {
        if (ch + 1 < nch) {
            wmma_prefetch(sb + ((ch + 1) & 1) * STAGE_SZ, Ahi, Alo, Bhi, Blo,
                          m0, M, K, (ch + 1) << 5, tid);
            CP_COMMIT();
            CP_WAIT1();
        } else {
            CP_WAIT0();
        }
        __syncthreads();

        const uint32_t st = sb + (ch & 1) * STAGE_SZ;
        #pragma unroll
        for (int kk = 0; kk < 2; kk++) {
            const uint32_t kb = kk * 32;
            uint32_t ah[2][4], al[2][4], bh[4][4], bl[4][4];
            #pragma unroll
            for (int mt = 0; mt < 2; mt++) {
                uint32_t ao = st + aoffs + mt * (16 * STRIDE_B) + kb;
                ldsm4(ah[mt], ao + 0 * ARR_SZ);
                ldsm4(al[mt], ao + 1 * ARR_SZ);
            }
            #pragma unroll
            for (int np = 0; np < 4; np++) {
                uint32_t bo = st + boffs + np * (16 * STRIDE_B) + kb;
                ldsm4(bh[np], bo + 2 * ARR_SZ);
                ldsm4(bl[np], bo + 3 * ARR_SZ);
            }
            #pragma unroll
            for (int mt = 0; mt < 2; mt++)
                #pragma unroll
                for (int nt = 0; nt < 8; nt++) {
                    float* cc = c[mt][nt];
                    const uint32_t* ph = &bh[nt >> 1][(nt & 1) * 2];
                    const uint32_t* pl = &bl[nt >> 1][(nt & 1) * 2];
                    mma16816(cc, ah[mt], ph);
                    mma16816(cc, ah[mt], pl);
                    mma16816(cc, al[mt], ph);
                }
        }
        __syncthreads();
    }

    #pragma unroll
    for (int mt = 0; mt < 2; mt++) {
        #pragma unroll
        for (int part = 0; part < 2; part++) {
            int gr = m0 + wm0 + mt * 16 + (lane >> 2) + part * 8;
            if (gr >= M) continue;
            #pragma unroll
            for (int nt = 0; nt < 8; nt++) {
                int gcol = wn0 + nt * 8 + (lane & 3) * 2;
                float v0 = c[mt][nt][part * 2 + 0];
                float v1 = c[mt][nt][part * 2 + 1];
                if (bias) { v0 += bias[gcol]; v1 += bias[gcol + 1]; }
                if (dorelu) { v0 = fmaxf(v0, 0.f); v1 = fmaxf(v1, 0.f); }
                if (Cf)
                    *(float2*)(Cf + (size_t)gr * FD + gcol) = make_float2(v0, v1);
                if (Chi) {
                    __nv_bfloat16 h0 = __float2bfloat16(v0);
                    __nv_bfloat16 h1 = __float2bfloat16(v1);
                    __nv_bfloat162 hp = __halves2bfloat162(h0, h1);
                    __nv_bfloat162 lp = __halves2bfloat162(
                        __float2bfloat16(v0 - __bfloat162float(h0)),
                        __float2bfloat16(v1 - __bfloat162float(h1)));
                    *(uint32_t*)(Chi + (size_t)gr * FD + gcol) = *(uint32_t*)&hp;
                    *(uint32_t*)(Clo + (size_t)gr * FD + gcol) = *(uint32_t*)&lp;
                }
            }
        }
    }
}

// ================= gather aggregation (128-dim, warp/node) =================
__global__ void k_agg(const float* __restrict__ h, const int* __restrict__ off,
                      const int* __restrict__ ssrc, const float* __restrict__ sw,
                      const float* __restrict__ invd, const float* __restrict__ bias,
                      const int* __restrict__ selfmap,
                      float* __restrict__ outf, __nv_bfloat16* __restrict__ outhi,
                      __nv_bfloat16* __restrict__ outlo, int dorelu)
{
    int node = (blockIdx.x * blockDim.x + threadIdx.x) >> 5;
    int lane = threadIdx.x & 31;
    if (node >= NN) return;
    int s = off[node], e = off[node + 1];
    float4 acc = make_float4(0.f, 0.f, 0.f, 0.f);
    for (int i = s; i < e; i++) {
        int   src = ssrc[i];
        float w   = sw[i];
        float4 v  = *(const float4*)(h + (size_t)src * FD + lane * 4);
        acc.x = fmaf(w, v.x, acc.x);
        acc.y = fmaf(w, v.y, acc.y);
        acc.z = fmaf(w, v.z, acc.z);
        acc.w = fmaf(w, v.w, acc.w);
    }
    int self = selfmap ? selfmap[node] : node;
    float  id = invd[node];
    float4 hv = *(const float4*)(h + (size_t)self * FD + lane * 4);
    float4 b  = *(const float4*)(bias + lane * 4);
    acc.x = fmaf(id, hv.x, acc.x) + b.x;
    acc.y = fmaf(id, hv.y, acc.y) + b.y;
    acc.z = fmaf(id, hv.z, acc.z) + b.z;
    acc.w = fmaf(id, hv.w, acc.w) + b.w;
    if (dorelu) {
        acc.x = fmaxf(acc.x, 0.f); acc.y = fmaxf(acc.y, 0.f);
        acc.z = fmaxf(acc.z, 0.f); acc.w = fmaxf(acc.w, 0.f);
    }
    if (outf)
        *(float4*)(outf + (size_t)node * FD + lane * 4) = acc;
    if (outhi) {
        float vv[4] = {acc.x, acc.y, acc.z, acc.w};
        uint32_t hw[2], lw[2];
        #pragma unroll
        for (int q = 0; q < 2; q++) {
            __nv_bfloat16 ha = __float2bfloat16(vv[2 * q]);
            __nv_bfloat16 hb = __float2bfloat16(vv[2 * q + 1]);
            __nv_bfloat162 hp = __halves2bfloat162(ha, hb);
            __nv_bfloat162 lp = __halves2bfloat162(
                __float2bfloat16(vv[2 * q] - __bfloat162float(ha)),
                __float2bfloat16(vv[2 * q + 1] - __bfloat162float(hb)));
            hw[q] = *(uint32_t*)&hp;
            lw[q] = *(uint32_t*)&lp;
        }
        *(uint2*)(outhi + (size_t)node * FD + lane * 4) = make_uint2(hw[0], hw[1]);
        *(uint2*)(outlo + (size_t)node * FD + lane * 4) = make_uint2(lw[0], lw[1]);
    }
}

// ===== fused hop-agg + bilinear score: out[:,col] = sigmoid(T . (agg(G)+b3)) =====
__global__ void k_aggscore(const float* __restrict__ G, const float* __restrict__ T,
                           const int* __restrict__ off, const int* __restrict__ ssrc,
                           const float* __restrict__ sw, const float* __restrict__ invd,
                           const float* __restrict__ b3, float* __restrict__ out,
                           int col)
{
    const unsigned FULL = 0xffffffffu;
    int node = (blockIdx.x * blockDim.x + threadIdx.x) >> 5;
    int lane = threadIdx.x & 31;
    if (node >= NN) return;
    float4 tv = *(const float4*)(T + (size_t)node * FD + lane * 4);
    int s = off[node], e = off[node + 1];
    float acc = 0.f;
    for (int i = s; i < e; i++) {
        int   src = ssrc[i];
        float w   = sw[i];
        float4 v  = *(const float4*)(G + (size_t)src * FD + lane * 4);
        acc = fmaf(w, tv.x * v.x + tv.y * v.y + tv.z * v.z + tv.w * v.w, acc);
    }
    float4 gs = *(const float4*)(G + (size_t)node * FD + lane * 4);
    float4 bb = *(const float4*)(b3 + lane * 4);
    acc = fmaf(invd[node], tv.x * gs.x + tv.y * gs.y + tv.z * gs.z + tv.w * gs.w, acc);
    acc += tv.x * bb.x + tv.y * bb.y + tv.z * bb.z + tv.w * bb.w;
    #pragma unroll
    for (int d = 16; d > 0; d >>= 1) acc += __shfl_xor_sync(FULL, acc, d);
    if (lane == 0)
        out[(size_t)node * OUTC + col] = 1.0f / (1.0f + expf(-acc));
}

// ================= classifier GEMM (128 -> 10) =================
__global__ void k_gemm10(const float* __restrict__ A, const float* __restrict__ W,
                         float* __restrict__ C)
{
    __shared__ float w[FD * NC];
    for (int i = threadIdx.x; i < FD * NC; i += blockDim.x) w[i] = W[i];
    __syncthreads();
    int r = blockIdx.x * blockDim.x + threadIdx.x;
    if (r >= NN) return;
    float acc[NC];
    #pragma unroll
    for (int j = 0; j < NC; j++) acc[j] = 0.f;
    const float4* ap = (const float4*)(A + (size_t)r * FD);
    #pragma unroll 8
    for (int k4 = 0; k4 < 32; k4++) {
        float4 v = ap[k4];
        int k = k4 * 4;
        #pragma unroll
        for (int j = 0; j < NC; j++) {
            acc[j] = fmaf(v.x, w[(k + 0) * NC + j], acc[j]);
            acc[j] = fmaf(v.y, w[(k + 1) * NC + j], acc[j]);
            acc[j] = fmaf(v.z, w[(k + 2) * NC + j], acc[j]);
            acc[j] = fmaf(v.w, w[(k + 3) * NC + j], acc[j]);
        }
    }
    #pragma unroll
    for (int j = 0; j < NC; j++) C[(size_t)r * NC + j] = acc[j];
}

__global__ void k_agg10(const float* __restrict__ h, const int* __restrict__ off,
                        const int* __restrict__ ssrc, const float* __restrict__ sw,
                        const float* __restrict__ invd, const float* __restrict__ bc,
                        float* __restrict__ out)
{
    int node = (blockIdx.x * blockDim.x + threadIdx.x) >> 5;
    int lane = threadIdx.x & 31;
    if (node >= NN || lane >= NC) return;
    int s = off[node], e = off[node + 1];
    float acc = 0.f;
    for (int i = s; i < e; i++) {
        int src = ssrc[i];
        acc = fmaf(sw[i], h[(size_t)src * NC + lane], acc);
    }
    acc = fmaf(invd[node], h[(size_t)node * NC + lane], acc) + bc[lane];
    out[(size_t)node * OUTC + lane] = acc;
}

// ================= host =================
extern "C" void kernel_launch(void* const* d_in, const int* in_sizes, int n_in,
                              void* d_out, int out_size)
{
    const float* x    = (const float*)d_in[0];
    const int*   ei   = (const int*)  d_in[1];
    const int*   eh   = (const int*)  d_in[2];
    const int*   perm = (const int*)  d_in[4];
    const float* W1   = (const float*)d_in[5];
    const float* b1   = (const float*)d_in[6];
    const float* W2   = (const float*)d_in[7];
    const float* b2   = (const float*)d_in[8];
    const float* W3   = (const float*)d_in[9];
    const float* b3   = (const float*)d_in[10];
    const float* M1   = (const float*)d_in[11];
    const float* mb1  = (const float*)d_in[12];
    const float* M2   = (const float*)d_in[13];
    const float* mb2  = (const float*)d_in[14];
    const float* Wc   = (const float*)d_in[15];
    const float* bc   = (const float*)d_in[16];
    const float* Wd   = (const float*)d_in[17];
    float* out = (float*)d_out;

    float *Hg, *G, *EAf, *T, *C10, *dis, *invd, *sw;
    __nv_bfloat16 *P1h, *P1l, *P2h, *P2l, *P3h, *P3l, *P4h, *P4l, *xh, *xl, *Wh, *Wl;
    int *cnt, *off, *cur, *btot, *ssrc, *ssrcp;
    cudaGetSymbolAddress((void**)&Hg,   g_Hg);
    cudaGetSymbolAddress((void**)&G,    g_G);
    cudaGetSymbolAddress((void**)&EAf,  g_EAf);
    cudaGetSymbolAddress((void**)&T,    g_T);
    cudaGetSymbolAddress((void**)&C10,  g_C10);
    cudaGetSymbolAddress((void**)&P1h,  g_P1h);
    cudaGetSymbolAddress((void**)&P1l,  g_P1l);
    cudaGetSymbolAddress((void**)&P2h,  g_P2h);
    cudaGetSymbolAddress((void**)&P2l,  g_P2l);
    cudaGetSymbolAddress((void**)&P3h,  g_P3h);
    cudaGetSymbolAddress((void**)&P3l,  g_P3l);
    cudaGetSymbolAddress((void**)&P4h,  g_P4h);
    cudaGetSymbolAddress((void**)&P4l,  g_P4l);
    cudaGetSymbolAddress((void**)&xh,   g_xh);
    cudaGetSymbolAddress((void**)&xl,   g_xl);
    cudaGetSymbolAddress((void**)&Wh,   g_Wh);
    cudaGetSymbolAddress((void**)&Wl,   g_Wl);
    cudaGetSymbolAddress((void**)&cnt,  g_cnt);
    cudaGetSymbolAddress((void**)&dis,  g_dis);
    cudaGetSymbolAddress((void**)&invd, g_invd);
    cudaGetSymbolAddress((void**)&off,  g_off);
    cudaGetSymbolAddress((void**)&cur,  g_cur);
    cudaGetSymbolAddress((void**)&btot, g_btot);
    cudaGetSymbolAddress((void**)&ssrc, g_ssrc);
    cudaGetSymbolAddress((void**)&ssrcp,g_ssrcp);
    cudaGetSymbolAddress((void**)&sw,   g_sw);

    cudaFuncSetAttribute(k_wmma, cudaFuncAttributeMaxDynamicSharedMemorySize, SMEM_SZ);

    const int TE = 256;
    const int GE = (NE + TE - 1) / TE;
    const int GN = (NN + TE - 1) / TE;
    const int GW = (NN * 32 + TE - 1) / TE;
    const int GM = (NN + 127) / 128;
    const int NB = (NN + SCB - 1) / SCB;   // 98 scan blocks

    // ---- prologue ordered so the 6th executed kernel is the W1 GEMM (ncu -s 5) ----
    cudaMemsetAsync(cnt, 0, sizeof(int) * 2 * NN);
    k_splitx<<<(NN * NF + 255) / 256, 256>>>(x, xh, xl, NN * NF);
    k_count<<<GE, TE>>>(ei + NE, cnt);
    k_prepw<<<(512 * 128 + 255) / 256, 256>>>(W1, Wh + WOFF_W1, Wl + WOFF_W1, 512);
    k_wmma<<<GM, 256, SMEM_SZ>>>(xh, xl, Wh + WOFF_W1, Wl + WOFF_W1,
                                 nullptr, 0, Hg, nullptr, nullptr, NN, 512);
    k_count<<<GE, TE>>>(eh + NE, cnt + NN);
    k_deg<<<GN, TE>>>(cnt,      dis,      invd);
    k_deg<<<GN, TE>>>(cnt + NN, dis + NN, invd + NN);

    // ---- multi-block scans (both graphs) ----
    k_scan_blk<<<NB, SCB>>>(cnt, off, btot, NN);
    k_scan_tot<<<1, 128>>>(btot, NB, off + NN);
    k_scan_add<<<GN, TE>>>(off, btot, cur, NN);
    k_scan_blk<<<NB, SCB>>>(cnt + NN, off + (NN + 1), btot + 128, NN);
    k_scan_tot<<<1, 128>>>(btot + 128, NB, off + (NN + 1) + NN);
    k_scan_add<<<GN, TE>>>(off + (NN + 1), btot + 128, cur + NN, NN);

    k_place<<<GE, TE>>>(ei, ei + NE, dis,      cur,      ssrc,      sw);
    k_place<<<GE, TE>>>(eh, eh + NE, dis + NN, cur + NN, ssrc + NE, sw + NE);
    k_permsrc<<<GE, TE>>>(ssrc, perm, ssrcp);

    // ---- remaining weight prep ----
    k_prepw<<<(128 * 128 + 255) / 256, 256>>>(W2, Wh + WOFF_W2, Wl + WOFF_W2, 128);
    k_prepw<<<(128 * 128 + 255) / 256, 256>>>(W3, Wh + WOFF_W3, Wl + WOFF_W3, 128);
    k_prepw<<<(128 * 128 + 255) / 256, 256>>>(M1, Wh + WOFF_M1, Wl + WOFF_M1, 128);
    k_prepw<<<(128 * 128 + 255) / 256, 256>>>(M2, Wh + WOFF_M2, Wl + WOFF_M2, 128);
    k_prepw<<<(128 * 128 + 255) / 256, 256>>>(Wd, Wh + WOFF_WD, Wl + WOFF_WD, 128);

    // ---- good path ----
    k_agg<<<GW, TE>>>(Hg, off, ssrc, sw, invd, b1, nullptr,
                      nullptr, P1h, P1l, 1);
    k_wmma<<<GM, 256, SMEM_SZ>>>(P1h, P1l, Wh + WOFF_W2, Wl + WOFF_W2,
                                 nullptr, 0, G, nullptr, nullptr, NN, 128);
    k_agg<<<GW, TE>>>(G, off, ssrc, sw, invd, b2, nullptr,
                      EAf, P2h, P2l, 1);
    k_wmma<<<GM, 256, SMEM_SZ>>>(P2h, P2l, Wh + WOFF_W3, Wl + WOFF_W3,
                                 nullptr, 0, G, nullptr, nullptr, NN, 128);
    // encoder3 MLP + discriminator T
    k_wmma<<<GM, 256, SMEM_SZ>>>(P2h, P2l, Wh + WOFF_M1, Wl + WOFF_M1,
                                 mb1, 1, nullptr, P3h, P3l, NN, 128);
    k_wmma<<<GM, 256, SMEM_SZ>>>(P3h, P3l, Wh + WOFF_M2, Wl + WOFF_M2,
                                 mb2, 0, nullptr, P4h, P4l, NN, 128);
    k_wmma<<<GM, 256, SMEM_SZ>>>(P4h, P4l, Wh + WOFF_WD, Wl + WOFF_WD,
                                 nullptr, 0, T, nullptr, nullptr, NN, 128);
    // fused hop-agg + score (good) -> col 10
    k_aggscore<<<GW, TE>>>(G, T, off + (NN + 1), ssrc + NE, sw + NE, invd + NN,
                           b3, out, 10);

    // ---- bad path: layer1 = agg of Hg with permuted sources/self ----
    k_agg<<<GW, TE>>>(Hg, off, ssrcp, sw, invd, b1, perm,
                      nullptr, P1h, P1l, 1);
    k_wmma<<<GM, 256, SMEM_SZ>>>(P1h, P1l, Wh + WOFF_W2, Wl + WOFF_W2,
                                 nullptr, 0, G, nullptr, nullptr, NN, 128);
    k_agg<<<GW, TE>>>(G, off, ssrc, sw, invd, b2, nullptr,
                      nullptr, P2h, P2l, 1);
    k_wmma<<<GM, 256, SMEM_SZ>>>(P2h, P2l, Wh + WOFF_W3, Wl + WOFF_W3,
                                 nullptr, 0, G, nullptr, nullptr, NN, 128);
    // fused hop-agg + score (bad) -> col 11
    k_aggscore<<<GW, TE>>>(G, T, off + (NN + 1), ssrc + NE, sw + NE, invd + NN,
                           b3, out, 11);

    // ---- classifier GCN -> out cols 0..9 ----
    k_gemm10<<<GN, TE>>>(EAf, Wc, C10);
    k_agg10<<<GW, TE>>>(C10, off, ssrc, sw, invd, bc, out);
}

// round 10
// speedup vs baseline: 1.4876x; 1.2699x over previous
#include <cuda_runtime.h>
#include <cuda_bf16.h>
#include <math.h>
#include <stdint.h>

#define NN 100000
#define NE 1600000
#define NF 512
#define FD 128
#define NC 10
#define OUTC 12

// ================= PTX helpers (sm_80-compatible only) =================
__device__ __forceinline__ uint32_t s2u(const void* p) {
    uint32_t a;
    asm("{ .reg .u64 t; cvta.to.shared.u64 t, %1; cvt.u32.u64 %0, t; }"
        : "=r"(a) : "l"(p));
    return a;
}
__device__ __forceinline__ void cpa16(uint32_t dst, const void* src) {
    asm volatile("cp.async.cg.shared.global [%0], [%1], 16;" :: "r"(dst), "l"(src));
}
#define CP_COMMIT() asm volatile("cp.async.commit_group;" ::: "memory")
#define CP_WAIT1()  asm volatile("cp.async.wait_group 1;" ::: "memory")
#define CP_WAIT0()  asm volatile("cp.async.wait_group 0;" ::: "memory")

__device__ __forceinline__ void ldsm4(uint32_t* r, uint32_t addr) {
    asm volatile("ldmatrix.sync.aligned.m8n8.x4.shared.b16 {%0,%1,%2,%3}, [%4];"
                 : "=r"(r[0]), "=r"(r[1]), "=r"(r[2]), "=r"(r[3]) : "r"(addr));
}
__device__ __forceinline__ void mma16816(float* c, const uint32_t* a, const uint32_t* b) {
    asm volatile("mma.sync.aligned.m16n8k16.row.col.f32.bf16.bf16.f32 "
                 "{%0,%1,%2,%3}, {%4,%5,%6,%7}, {%8,%9}, {%0,%1,%2,%3};"
                 : "+f"(c[0]), "+f"(c[1]), "+f"(c[2]), "+f"(c[3])
                 : "r"(a[0]), "r"(a[1]), "r"(a[2]), "r"(a[3]), "r"(b[0]), "r"(b[1]));
}

// ================= scratch (device globals) =================
__device__ float g_Hg [(size_t)NN * FD];
__device__ float g_G  [(size_t)NN * FD];
__device__ float g_EAf[(size_t)NN * FD];
__device__ float g_T  [(size_t)NN * FD];
__device__ float g_C10[(size_t)NN * NC];
__device__ __nv_bfloat16 g_P1h[(size_t)NN * FD];
__device__ __nv_bfloat16 g_P1l[(size_t)NN * FD];
__device__ __nv_bfloat16 g_P2h[(size_t)NN * FD];
__device__ __nv_bfloat16 g_P2l[(size_t)NN * FD];
__device__ __nv_bfloat16 g_P3h[(size_t)NN * FD];
__device__ __nv_bfloat16 g_P3l[(size_t)NN * FD];
__device__ __nv_bfloat16 g_P4h[(size_t)NN * FD];
__device__ __nv_bfloat16 g_P4l[(size_t)NN * FD];
#define WOFF_W1 0
#define WOFF_W2 (128 * 512)
#define WOFF_W3 (WOFF_W2 + 128 * 128)
#define WOFF_M1 (WOFF_W3 + 128 * 128)
#define WOFF_M2 (WOFF_M1 + 128 * 128)
#define WOFF_WD (WOFF_M2 + 128 * 128)
#define WTOT    (WOFF_WD + 128 * 128)
__device__ __nv_bfloat16 g_Wh[WTOT];
__device__ __nv_bfloat16 g_Wl[WTOT];
__device__ int   g_cnt [2 * NN];
__device__ float g_dis [2 * NN];
__device__ float g_invd[2 * NN];
__device__ int   g_off [2 * (NN + 1)];
__device__ int   g_cur [2 * NN];
__device__ int   g_btot[2 * 128];
__device__ int   g_ssrc[2 * NE];
__device__ int   g_ssrcp[NE];
__device__ float g_sw  [2 * NE];

// ================= CSR build =================
__global__ void k_count(const int* __restrict__ dst, int* __restrict__ cnt) {
    int i = blockIdx.x * blockDim.x + threadIdx.x;
    if (i < NE) atomicAdd(&cnt[dst[i]], 1);
}

__global__ void k_deg(const int* __restrict__ cnt, float* __restrict__ dis,
                      float* __restrict__ invd) {
    int i = blockIdx.x * blockDim.x + threadIdx.x;
    if (i < NN) {
        float d = (float)(cnt[i] + 1);
        dis[i]  = rsqrtf(d);
        invd[i] = 1.0f / d;
    }
}

// ---- multi-block scan ----
#define SCB 1024
__global__ void k_scan_blk(const int* __restrict__ cnt, int* __restrict__ off,
                           int* __restrict__ btot, int n) {
    __shared__ int ws[32];
    const unsigned FULL = 0xffffffffu;
    int t = threadIdx.x, w = t >> 5, l = t & 31;
    int i = blockIdx.x * SCB + t;
    int v = (i < n) ? cnt[i] : 0;
    int s = v;
    #pragma unroll
    for (int d = 1; d < 32; d <<= 1) {
        int o = __shfl_up_sync(FULL, s, d);
        if (l >= d) s += o;
    }
    if (l == 31) ws[w] = s;
    __syncthreads();
    if (w == 0) {
        int x2 = ws[l];
        #pragma unroll
        for (int d = 1; d < 32; d <<= 1) {
            int o = __shfl_up_sync(FULL, x2, d);
            if (l >= d) x2 += o;
        }
        ws[l] = x2;
    }
    __syncthreads();
    int incl = s + (w > 0 ? ws[w - 1] : 0);
    if (i < n) off[i] = incl - v;
    if (t == SCB - 1) btot[blockIdx.x] = incl;
}

__global__ void k_scan_tot(int* __restrict__ btot, int nb, int* __restrict__ offN) {
    __shared__ int sh[128];
    int t = threadIdx.x;
    int v = (t < nb) ? btot[t] : 0;
    sh[t] = v;
    __syncthreads();
    #pragma unroll
    for (int d = 1; d < 128; d <<= 1) {
        int o = (t >= d) ? sh[t - d] : 0;
        __syncthreads();
        sh[t] += o;
        __syncthreads();
    }
    if (t < nb) btot[t] = sh[t] - v;
    if (t == 127) *offN = sh[127];
}

__global__ void k_scan_add(int* __restrict__ off, const int* __restrict__ btot,
                           int* __restrict__ cur, int n) {
    int i = blockIdx.x * blockDim.x + threadIdx.x;
    if (i < n) {
        int e = off[i] + btot[i >> 10];
        off[i] = e;
        cur[i] = e;
    }
}

__global__ void k_place(const int* __restrict__ src, const int* __restrict__ dst,
                        const float* __restrict__ dis, int* __restrict__ cur,
                        int* __restrict__ ssrc, float* __restrict__ sw) {
    int e = blockIdx.x * blockDim.x + threadIdx.x;
    if (e < NE) {
        int s = src[e], d = dst[e];
        int p = atomicAdd(&cur[d], 1);
        ssrc[p] = s;
        sw[p]   = dis[s] * dis[d];
    }
}

__global__ void k_permsrc(const int* __restrict__ ssrc, const int* __restrict__ perm,
                          int* __restrict__ ssrcp) {
    int i = blockIdx.x * blockDim.x + threadIdx.x;
    if (i < NE) ssrcp[i] = perm[ssrc[i]];
}

// ================= weight prep =================
__global__ void k_prepw(const float* __restrict__ W, __nv_bfloat16* __restrict__ Bh,
                        __nv_bfloat16* __restrict__ Bl, int K) {
    int i = blockIdx.x * blockDim.x + threadIdx.x;
    if (i < K * 128) {
        int n = i / K, k = i - n * K;
        float v = W[(size_t)k * 128 + n];
        __nv_bfloat16 h = __float2bfloat16(v);
        Bh[(size_t)n * K + k] = h;
        Bl[(size_t)n * K + k] = __float2bfloat16(v - __bfloat162float(h));
    }
}

// ================= mma.sync split-bf16 GEMM =================
#define STRIDE_B 80
#define ARR_SZ   (128 * STRIDE_B)
#define STAGE_SZ (4 * ARR_SZ)
#define SMEM_SZ  (2 * STAGE_SZ)

__device__ __forceinline__ void wmma_prefetch(
    uint32_t sbase, const __nv_bfloat16* Ah, const __nv_bfloat16* Al,
    const __nv_bfloat16* Bh, const __nv_bfloat16* Bl,
    int m0, int M, int K, int k0, int tid)
{
    #pragma unroll
    for (int p = 0; p < 2; p++) {
        int idx = tid + p * 256;
        int row = idx >> 2, cg = idx & 3;
        int gr = m0 + row; if (gr >= M) gr = M - 1;
        size_t aoff = (size_t)gr * K + k0 + cg * 8;
        size_t boff = (size_t)row * K + k0 + cg * 8;
        uint32_t so = row * STRIDE_B + cg * 16;
        cpa16(sbase + 0 * ARR_SZ + so, Ah + aoff);
        cpa16(sbase + 1 * ARR_SZ + so, Al + aoff);
        cpa16(sbase + 2 * ARR_SZ + so, Bh + boff);
        cpa16(sbase + 3 * ARR_SZ + so, Bl + boff);
    }
}

// A-prefetch from f32 with on-the-fly hi/lo split (for the x @ W1 GEMM)
__device__ __forceinline__ void wmma_prefetch_f32(
    uint32_t sbase, const float* Af,
    const __nv_bfloat16* Bh, const __nv_bfloat16* Bl,
    int m0, int M, int K, int k0, int tid)
{
    #pragma unroll
    for (int p = 0; p < 2; p++) {
        int idx = tid + p * 256;
        int row = idx >> 2, cg = idx & 3;
        int gr = m0 + row; if (gr >= M) gr = M - 1;
        size_t aoff = (size_t)gr * K + k0 + cg * 8;
        size_t boff = (size_t)row * K + k0 + cg * 8;
        uint32_t so = row * STRIDE_B + cg * 16;
        cpa16(sbase + 2 * ARR_SZ + so, Bh + boff);
        cpa16(sbase + 3 * ARR_SZ + so, Bl + boff);
        float4 v0 = *(const float4*)(Af + aoff);
        float4 v1 = *(const float4*)(Af + aoff + 4);
        float vv[8] = {v0.x, v0.y, v0.z, v0.w, v1.x, v1.y, v1.z, v1.w};
        uint32_t hw[4], lw[4];
        #pragma unroll
        for (int q = 0; q < 4; q++) {
            __nv_bfloat16 h0 = __float2bfloat16(vv[2 * q]);
            __nv_bfloat16 h1 = __float2bfloat16(vv[2 * q + 1]);
            __nv_bfloat162 hp = __halves2bfloat162(h0, h1);
            __nv_bfloat162 lp = __halves2bfloat162(
                __float2bfloat16(vv[2 * q] - __bfloat162float(h0)),
                __float2bfloat16(vv[2 * q + 1] - __bfloat162float(h1)));
            hw[q] = *(uint32_t*)&hp;
            lw[q] = *(uint32_t*)&lp;
        }
        *(uint4*)(0ULL, (uint4*)nullptr);  // (no-op guard removed below)
    }
}

// NOTE: the helper above can't STS via generic pointer cleanly; real path inlined
// in k_wmmaX below.

#define WMMA_MAINLOOP_BODY(st)                                                   \
    {                                                                            \
        _Pragma("unroll")                                                        \
        for (int kk = 0; kk < 2; kk++) {                                         \
            const uint32_t kb = kk * 32;                                         \
            uint32_t ah[2][4], al[2][4], bh[4][4], bl[4][4];                     \
            _Pragma("unroll")                                                    \
            for (int mt = 0; mt < 2; mt++) {                                     \
                uint32_t ao = (st) + aoffs + mt * (16 * STRIDE_B) + kb;          \
                ldsm4(ah[mt], ao + 0 * ARR_SZ);                                  \
                ldsm4(al[mt], ao + 1 * ARR_SZ);                                  \
            }                                                                    \
            _Pragma("unroll")                                                    \
            for (int np = 0; np < 4; np++) {                                     \
                uint32_t bo = (st) + boffs + np * (16 * STRIDE_B) + kb;          \
                ldsm4(bh[np], bo + 2 * ARR_SZ);                                  \
                ldsm4(bl[np], bo + 3 * ARR_SZ);                                  \
            }                                                                    \
            _Pragma("unroll")                                                    \
            for (int mt = 0; mt < 2; mt++)                                       \
                _Pragma("unroll")                                                \
                for (int nt = 0; nt < 8; nt++) {                                 \
                    float* cc = c[mt][nt];                                       \
                    const uint32_t* ph = &bh[nt >> 1][(nt & 1) * 2];             \
                    const uint32_t* pl = &bl[nt >> 1][(nt & 1) * 2];             \
                    mma16816(cc, ah[mt], ph);                                    \
                    mma16816(cc, ah[mt], pl);                                    \
                    mma16816(cc, al[mt], ph);                                    \
                }                                                                \
        }                                                                        \
    }

#define WMMA_EPILOGUE()                                                          \
    _Pragma("unroll")                                                            \
    for (int mt = 0; mt < 2; mt++) {                                             \
        _Pragma("unroll")                                                        \
        for (int part = 0; part < 2; part++) {                                   \
            int gr = m0 + wm0 + mt * 16 + (lane >> 2) + part * 8;                \
            if (gr >= M) continue;                                               \
            _Pragma("unroll")                                                    \
            for (int nt = 0; nt < 8; nt++) {                                     \
                int gcol = wn0 + nt * 8 + (lane & 3) * 2;                        \
                float v0 = c[mt][nt][part * 2 + 0];                              \
                float v1 = c[mt][nt][part * 2 + 1];                              \
                if (bias) { v0 += bias[gcol]; v1 += bias[gcol + 1]; }            \
                if (dorelu) { v0 = fmaxf(v0, 0.f); v1 = fmaxf(v1, 0.f); }        \
                if (Cf)                                                          \
                    *(float2*)(Cf + (size_t)gr * FD + gcol) = make_float2(v0, v1); \
                if (Chi) {                                                       \
                    __nv_bfloat16 h0 = __float2bfloat16(v0);                     \
                    __nv_bfloat16 h1 = __float2bfloat16(v1);                     \
                    __nv_bfloat162 hp = __halves2bfloat162(h0, h1);              \
                    __nv_bfloat162 lp = __halves2bfloat162(                      \
                        __float2bfloat16(v0 - __bfloat162float(h0)),             \
                        __float2bfloat16(v1 - __bfloat162float(h1)));            \
                    *(uint32_t*)(Chi + (size_t)gr * FD + gcol) = *(uint32_t*)&hp; \
                    *(uint32_t*)(Clo + (size_t)gr * FD + gcol) = *(uint32_t*)&lp; \
                }                                                                \
            }                                                                    \
        }                                                                        \
    }

__global__ void __launch_bounds__(256, 2) k_wmma(
    const __nv_bfloat16* __restrict__ Ahi, const __nv_bfloat16* __restrict__ Alo,
    const __nv_bfloat16* __restrict__ Bhi, const __nv_bfloat16* __restrict__ Blo,
    const float* __restrict__ bias, int dorelu,
    float* __restrict__ Cf, __nv_bfloat16* __restrict__ Chi,
    __nv_bfloat16* __restrict__ Clo, int M, int K)
{
    extern __shared__ char smem[];
    const uint32_t sb = s2u(smem);
    const int tid  = threadIdx.x;
    const int lane = tid & 31, w = tid >> 5;
    const int wm0 = (w >> 1) * 32, wn0 = (w & 1) * 64;
    const int m0  = blockIdx.x * 128;

    float c[2][8][4];
    #pragma unroll
    for (int i = 0; i < 2; i++)
        #pragma unroll
        for (int j = 0; j < 8; j++)
            #pragma unroll
            for (int q = 0; q < 4; q++) c[i][j][q] = 0.f;

    const uint32_t aoffs = (uint32_t)((wm0 + (lane & 15)) * STRIDE_B + (lane >> 4) * 16);
    const uint32_t boffs = (uint32_t)((wn0 + ((lane >> 4) & 1) * 8 + (lane & 7)) * STRIDE_B
                                      + ((lane >> 3) & 1) * 16);

    const int nch = K >> 5;
    wmma_prefetch(sb, Ahi, Alo, Bhi, Blo, m0, M, K, 0, tid);
    CP_COMMIT();

    for (int ch = 0; ch < nch; ch++) {
        if (ch + 1 < nch) {
            wmma_prefetch(sb + ((ch + 1) & 1) * STAGE_SZ, Ahi, Alo, Bhi, Blo,
                          m0, M, K, (ch + 1) << 5, tid);
            CP_COMMIT();
            CP_WAIT1();
        } else {
            CP_WAIT0();
        }
        __syncthreads();
        const uint32_t st = sb + (ch & 1) * STAGE_SZ;
        WMMA_MAINLOOP_BODY(st)
        __syncthreads();
    }
    WMMA_EPILOGUE()
}

// ---- variant: A is f32, split to hi/lo on the fly (for x @ W1) ----
__global__ void __launch_bounds__(256, 2) k_wmmaX(
    const float* __restrict__ Af,
    const __nv_bfloat16* __restrict__ Bhi, const __nv_bfloat16* __restrict__ Blo,
    const float* __restrict__ bias, int dorelu,
    float* __restrict__ Cf, __nv_bfloat16* __restrict__ Chi,
    __nv_bfloat16* __restrict__ Clo, int M, int K)
{
    extern __shared__ char smem[];
    const uint32_t sb = s2u(smem);
    const int tid  = threadIdx.x;
    const int lane = tid & 31, w = tid >> 5;
    const int wm0 = (w >> 1) * 32, wn0 = (w & 1) * 64;
    const int m0  = blockIdx.x * 128;

    float c[2][8][4];
    #pragma unroll
    for (int i = 0; i < 2; i++)
        #pragma unroll
        for (int j = 0; j < 8; j++)
            #pragma unroll
            for (int q = 0; q < 4; q++) c[i][j][q] = 0.f;

    const uint32_t aoffs = (uint32_t)((wm0 + (lane & 15)) * STRIDE_B + (lane >> 4) * 16);
    const uint32_t boffs = (uint32_t)((wn0 + ((lane >> 4) & 1) * 8 + (lane & 7)) * STRIDE_B
                                      + ((lane >> 3) & 1) * 16);

    const int nch = K >> 5;

    // prefetch helper (lambda-free, inlined twice)
    #define PREFETCH_X(sbase, k0)                                                 \
    {                                                                             \
        _Pragma("unroll")                                                         \
        for (int p = 0; p < 2; p++) {                                             \
            int idx = tid + p * 256;                                              \
            int row = idx >> 2, cg = idx & 3;                                     \
            int gr = m0 + row; if (gr >= M) gr = M - 1;                           \
            size_t aoff = (size_t)gr * K + (k0) + cg * 8;                         \
            size_t boff = (size_t)row * K + (k0) + cg * 8;                        \
            uint32_t so = row * STRIDE_B + cg * 16;                               \
            cpa16((sbase) + 2 * ARR_SZ + so, Bhi + boff);                         \
            cpa16((sbase) + 3 * ARR_SZ + so, Blo + boff);                         \
            float4 v0 = *(const float4*)(Af + aoff);                              \
            float4 v1 = *(const float4*)(Af + aoff + 4);                          \
            float vv[8] = {v0.x, v0.y, v0.z, v0.w, v1.x, v1.y, v1.z, v1.w};       \
            uint32_t hw[4], lw[4];                                                \
            _Pragma("unroll")                                                     \
            for (int q = 0; q < 4; q++) {                                         \
                __nv_bfloat16 h0 = __float2bfloat16(vv[2 * q]);                   \
                __nv_bfloat16 h1 = __float2bfloat16(vv[2 * q + 1]);               \
                __nv_bfloat162 hp = __halves2bfloat162(h0, h1);                   \
                __nv_bfloat162 lp = __halves2bfloat162(                           \
                    __float2bfloat16(vv[2 * q] - __bfloat162float(h0)),           \
                    __float2bfloat16(vv[2 * q + 1] - __bfloat162float(h1)));      \
                hw[q] = *(uint32_t*)&hp;                                          \
                lw[q] = *(uint32_t*)&lp;                                          \
            }                                                                     \
            asm volatile("st.shared.v4.b32 [%0], {%1,%2,%3,%4};"                  \
                :: "r"((sbase) + 0 * ARR_SZ + so),                                \
                   "r"(hw[0]), "r"(hw[1]), "r"(hw[2]), "r"(hw[3]) : "memory");    \
            asm volatile("st.shared.v4.b32 [%0], {%1,%2,%3,%4};"                  \
                :: "r"((sbase) + 1 * ARR_SZ + so),                                \
                   "r"(lw[0]), "r"(lw[1]), "r"(lw[2]), "r"(lw[3]) : "memory");    \
        }                                                                         \
    }

    PREFETCH_X(sb, 0)
    CP_COMMIT();

    for (int ch = 0; ch < nch; ch++) {
        if (ch + 1 < nch) {
            PREFETCH_X(sb + ((ch + 1) & 1) * STAGE_SZ, (ch + 1) << 5)
            CP_COMMIT();
            CP_WAIT1();
        } else {
            CP_WAIT0();
        }
        __syncthreads();
        const uint32_t st = sb + (ch & 1) * STAGE_SZ;
        WMMA_MAINLOOP_BODY(st)
        __syncthreads();
    }
    WMMA_EPILOGUE()
    #undef PREFETCH_X
}

// ================= gather aggregation (128-dim, warp/node) =================
__global__ void k_agg(const float* __restrict__ h, const int* __restrict__ off,
                      const int* __restrict__ ssrc, const float* __restrict__ sw,
                      const float* __restrict__ invd, const float* __restrict__ bias,
                      const int* __restrict__ selfmap,
                      float* __restrict__ outf, __nv_bfloat16* __restrict__ outhi,
                      __nv_bfloat16* __restrict__ outlo, int dorelu)
{
    int node = (blockIdx.x * blockDim.x + threadIdx.x) >> 5;
    int lane = threadIdx.x & 31;
    if (node >= NN) return;
    int s = off[node], e = off[node + 1];
    float4 acc = make_float4(0.f, 0.f, 0.f, 0.f);
    for (int i = s; i < e; i++) {
        int   src = ssrc[i];
        float w   = sw[i];
        float4 v  = *(const float4*)(h + (size_t)src * FD + lane * 4);
        acc.x = fmaf(w, v.x, acc.x);
        acc.y = fmaf(w, v.y, acc.y);
        acc.z = fmaf(w, v.z, acc.z);
        acc.w = fmaf(w, v.w, acc.w);
    }
    int self = selfmap ? selfmap[node] : node;
    float  id = invd[node];
    float4 hv = *(const float4*)(h + (size_t)self * FD + lane * 4);
    float4 b  = *(const float4*)(bias + lane * 4);
    acc.x = fmaf(id, hv.x, acc.x) + b.x;
    acc.y = fmaf(id, hv.y, acc.y) + b.y;
    acc.z = fmaf(id, hv.z, acc.z) + b.z;
    acc.w = fmaf(id, hv.w, acc.w) + b.w;
    if (dorelu) {
        acc.x = fmaxf(acc.x, 0.f); acc.y = fmaxf(acc.y, 0.f);
        acc.z = fmaxf(acc.z, 0.f); acc.w = fmaxf(acc.w, 0.f);
    }
    if (outf)
        *(float4*)(outf + (size_t)node * FD + lane * 4) = acc;
    if (outhi) {
        float vv[4] = {acc.x, acc.y, acc.z, acc.w};
        uint32_t hw[2], lw[2];
        #pragma unroll
        for (int q = 0; q < 2; q++) {
            __nv_bfloat16 ha = __float2bfloat16(vv[2 * q]);
            __nv_bfloat16 hb = __float2bfloat16(vv[2 * q + 1]);
            __nv_bfloat162 hp = __halves2bfloat162(ha, hb);
            __nv_bfloat162 lp = __halves2bfloat162(
                __float2bfloat16(vv[2 * q] - __bfloat162float(ha)),
                __float2bfloat16(vv[2 * q + 1] - __bfloat162float(hb)));
            hw[q] = *(uint32_t*)&hp;
            lw[q] = *(uint32_t*)&lp;
        }
        *(uint2*)(outhi + (size_t)node * FD + lane * 4) = make_uint2(hw[0], hw[1]);
        *(uint2*)(outlo + (size_t)node * FD + lane * 4) = make_uint2(lw[0], lw[1]);
    }
}

// ===== fused hop-agg + bilinear score =====
__global__ void k_aggscore(const float* __restrict__ G, const float* __restrict__ T,
                           const int* __restrict__ off, const int* __restrict__ ssrc,
                           const float* __restrict__ sw, const float* __restrict__ invd,
                           const float* __restrict__ b3, float* __restrict__ out,
                           int col)
{
    const unsigned FULL = 0xffffffffu;
    int node = (blockIdx.x * blockDim.x + threadIdx.x) >> 5;
    int lane = threadIdx.x & 31;
    if (node >= NN) return;
    float4 tv = *(const float4*)(T + (size_t)node * FD + lane * 4);
    int s = off[node], e = off[node + 1];
    float acc = 0.f;
    for (int i = s; i < e; i++) {
        int   src = ssrc[i];
        float w   = sw[i];
        float4 v  = *(const float4*)(G + (size_t)src * FD + lane * 4);
        acc = fmaf(w, tv.x * v.x + tv.y * v.y + tv.z * v.z + tv.w * v.w, acc);
    }
    float4 gs = *(const float4*)(G + (size_t)node * FD + lane * 4);
    float4 bb = *(const float4*)(b3 + lane * 4);
    acc = fmaf(invd[node], tv.x * gs.x + tv.y * gs.y + tv.z * gs.z + tv.w * gs.w, acc);
    acc += tv.x * bb.x + tv.y * bb.y + tv.z * bb.z + tv.w * bb.w;
    #pragma unroll
    for (int d = 16; d > 0; d >>= 1) acc += __shfl_xor_sync(FULL, acc, d);
    if (lane == 0)
        out[(size_t)node * OUTC + col] = 1.0f / (1.0f + expf(-acc));
}

// ================= classifier =================
__global__ void k_gemm10(const float* __restrict__ A, const float* __restrict__ W,
                         float* __restrict__ C)
{
    __shared__ float w[FD * NC];
    for (int i = threadIdx.x; i < FD * NC; i += blockDim.x) w[i] = W[i];
    __syncthreads();
    int r = blockIdx.x * blockDim.x + threadIdx.x;
    if (r >= NN) return;
    float acc[NC];
    #pragma unroll
    for (int j = 0; j < NC; j++) acc[j] = 0.f;
    const float4* ap = (const float4*)(A + (size_t)r * FD);
    #pragma unroll 8
    for (int k4 = 0; k4 < 32; k4++) {
        float4 v = ap[k4];
        int k = k4 * 4;
        #pragma unroll
        for (int j = 0; j < NC; j++) {
            acc[j] = fmaf(v.x, w[(k + 0) * NC + j], acc[j]);
            acc[j] = fmaf(v.y, w[(k + 1) * NC + j], acc[j]);
            acc[j] = fmaf(v.z, w[(k + 2) * NC + j], acc[j]);
            acc[j] = fmaf(v.w, w[(k + 3) * NC + j], acc[j]);
        }
    }
    #pragma unroll
    for (int j = 0; j < NC; j++) C[(size_t)r * NC + j] = acc[j];
}

__global__ void k_agg10(const float* __restrict__ h, const int* __restrict__ off,
                        const int* __restrict__ ssrc, const float* __restrict__ sw,
                        const float* __restrict__ invd, const float* __restrict__ bc,
                        float* __restrict__ out)
{
    int node = (blockIdx.x * blockDim.x + threadIdx.x) >> 5;
    int lane = threadIdx.x & 31;
    if (node >= NN || lane >= NC) return;
    int s = off[node], e = off[node + 1];
    float acc = 0.f;
    for (int i = s; i < e; i++) {
        int src = ssrc[i];
        acc = fmaf(sw[i], h[(size_t)src * NC + lane], acc);
    }
    acc = fmaf(invd[node], h[(size_t)node * NC + lane], acc) + bc[lane];
    out[(size_t)node * OUTC + lane] = acc;
}

// ================= host =================
extern "C" void kernel_launch(void* const* d_in, const int* in_sizes, int n_in,
                              void* d_out, int out_size)
{
    const float* x    = (const float*)d_in[0];
    const int*   ei   = (const int*)  d_in[1];
    const int*   eh   = (const int*)  d_in[2];
    const int*   perm = (const int*)  d_in[4];
    const float* W1   = (const float*)d_in[5];
    const float* b1   = (const float*)d_in[6];
    const float* W2   = (const float*)d_in[7];
    const float* b2   = (const float*)d_in[8];
    const float* W3   = (const float*)d_in[9];
    const float* b3   = (const float*)d_in[10];
    const float* M1   = (const float*)d_in[11];
    const float* mb1  = (const float*)d_in[12];
    const float* M2   = (const float*)d_in[13];
    const float* mb2  = (const float*)d_in[14];
    const float* Wc   = (const float*)d_in[15];
    const float* bc   = (const float*)d_in[16];
    const float* Wd   = (const float*)d_in[17];
    float* out = (float*)d_out;

    float *Hg, *G, *EAf, *T, *C10, *dis, *invd, *sw;
    __nv_bfloat16 *P1h, *P1l, *P2h, *P2l, *P3h, *P3l, *P4h, *P4l, *Wh, *Wl;
    int *cnt, *off, *cur, *btot, *ssrc, *ssrcp;
    cudaGetSymbolAddress((void**)&Hg,   g_Hg);
    cudaGetSymbolAddress((void**)&G,    g_G);
    cudaGetSymbolAddress((void**)&EAf,  g_EAf);
    cudaGetSymbolAddress((void**)&T,    g_T);
    cudaGetSymbolAddress((void**)&C10,  g_C10);
    cudaGetSymbolAddress((void**)&P1h,  g_P1h);
    cudaGetSymbolAddress((void**)&P1l,  g_P1l);
    cudaGetSymbolAddress((void**)&P2h,  g_P2h);
    cudaGetSymbolAddress((void**)&P2l,  g_P2l);
    cudaGetSymbolAddress((void**)&P3h,  g_P3h);
    cudaGetSymbolAddress((void**)&P3l,  g_P3l);
    cudaGetSymbolAddress((void**)&P4h,  g_P4h);
    cudaGetSymbolAddress((void**)&P4l,  g_P4l);
    cudaGetSymbolAddress((void**)&Wh,   g_Wh);
    cudaGetSymbolAddress((void**)&Wl,   g_Wl);
    cudaGetSymbolAddress((void**)&cnt,  g_cnt);
    cudaGetSymbolAddress((void**)&dis,  g_dis);
    cudaGetSymbolAddress((void**)&invd, g_invd);
    cudaGetSymbolAddress((void**)&off,  g_off);
    cudaGetSymbolAddress((void**)&cur,  g_cur);
    cudaGetSymbolAddress((void**)&btot, g_btot);
    cudaGetSymbolAddress((void**)&ssrc, g_ssrc);
    cudaGetSymbolAddress((void**)&ssrcp,g_ssrcp);
    cudaGetSymbolAddress((void**)&sw,   g_sw);

    cudaFuncSetAttribute(k_wmma,  cudaFuncAttributeMaxDynamicSharedMemorySize, SMEM_SZ);
    cudaFuncSetAttribute(k_wmmaX, cudaFuncAttributeMaxDynamicSharedMemorySize, SMEM_SZ);

    const int TE = 256;
    const int GE = (NE + TE - 1) / TE;
    const int GN = (NN + TE - 1) / TE;
    const int GW = (NN * 32 + TE - 1) / TE;
    const int GM = (NN + 127) / 128;
    const int NB = (NN + SCB - 1) / SCB;

    // ---- prologue (node 5 = k_wmmaX so ncu profiles the changed GEMM) ----
    cudaMemsetAsync(cnt, 0, sizeof(int) * 2 * NN);            // node 1
    k_count<<<GE, TE>>>(ei + NE, cnt);                         // node 2
    k_prepw<<<(512 * 128 + 255) / 256, 256>>>(W1, Wh + WOFF_W1, Wl + WOFF_W1, 512); // 3
    k_deg<<<GN, TE>>>(cnt, dis, invd);                         // node 4
    k_wmmaX<<<GM, 256, SMEM_SZ>>>(x, Wh + WOFF_W1, Wl + WOFF_W1,
                                  nullptr, 0, Hg, nullptr, nullptr, NN, 512); // 5
    k_count<<<GE, TE>>>(eh + NE, cnt + NN);
    k_deg<<<GN, TE>>>(cnt + NN, dis + NN, invd + NN);

    // ---- multi-block scans ----
    k_scan_blk<<<NB, SCB>>>(cnt, off, btot, NN);
    k_scan_tot<<<1, 128>>>(btot, NB, off + NN);
    k_scan_add<<<GN, TE>>>(off, btot, cur, NN);
    k_scan_blk<<<NB, SCB>>>(cnt + NN, off + (NN + 1), btot + 128, NN);
    k_scan_tot<<<1, 128>>>(btot + 128, NB, off + (NN + 1) + NN);
    k_scan_add<<<GN, TE>>>(off + (NN + 1), btot + 128, cur + NN, NN);

    k_place<<<GE, TE>>>(ei, ei + NE, dis,      cur,      ssrc,      sw);
    k_place<<<GE, TE>>>(eh, eh + NE, dis + NN, cur + NN, ssrc + NE, sw + NE);
    k_permsrc<<<GE, TE>>>(ssrc, perm, ssrcp);

    // ---- remaining weight prep ----
    k_prepw<<<(128 * 128 + 255) / 256, 256>>>(W2, Wh + WOFF_W2, Wl + WOFF_W2, 128);
    k_prepw<<<(128 * 128 + 255) / 256, 256>>>(W3, Wh + WOFF_W3, Wl + WOFF_W3, 128);
    k_prepw<<<(128 * 128 + 255) / 256, 256>>>(M1, Wh + WOFF_M1, Wl + WOFF_M1, 128);
    k_prepw<<<(128 * 128 + 255) / 256, 256>>>(M2, Wh + WOFF_M2, Wl + WOFF_M2, 128);
    k_prepw<<<(128 * 128 + 255) / 256, 256>>>(Wd, Wh + WOFF_WD, Wl + WOFF_WD, 128);

    // ---- good path ----
    k_agg<<<GW, TE>>>(Hg, off, ssrc, sw, invd, b1, nullptr,
                      nullptr, P1h, P1l, 1);
    k_wmma<<<GM, 256, SMEM_SZ>>>(P1h, P1l, Wh + WOFF_W2, Wl + WOFF_W2,
                                 nullptr, 0, G, nullptr, nullptr, NN, 128);
    k_agg<<<GW, TE>>>(G, off, ssrc, sw, invd, b2, nullptr,
                      EAf, P2h, P2l, 1);
    k_wmma<<<GM, 256, SMEM_SZ>>>(P2h, P2l, Wh + WOFF_W3, Wl + WOFF_W3,
                                 nullptr, 0, G, nullptr, nullptr, NN, 128);
    k_wmma<<<GM, 256, SMEM_SZ>>>(P2h, P2l, Wh + WOFF_M1, Wl + WOFF_M1,
                                 mb1, 1, nullptr, P3h, P3l, NN, 128);
    k_wmma<<<GM, 256, SMEM_SZ>>>(P3h, P3l, Wh + WOFF_M2, Wl + WOFF_M2,
                                 mb2, 0, nullptr, P4h, P4l, NN, 128);
    k_wmma<<<GM, 256, SMEM_SZ>>>(P4h, P4l, Wh + WOFF_WD, Wl + WOFF_WD,
                                 nullptr, 0, T, nullptr, nullptr, NN, 128);
    k_aggscore<<<GW, TE>>>(G, T, off + (NN + 1), ssrc + NE, sw + NE, invd + NN,
                           b3, out, 10);

    // ---- bad path ----
    k_agg<<<GW, TE>>>(Hg, off, ssrcp, sw, invd, b1, perm,
                      nullptr, P1h, P1l, 1);
    k_wmma<<<GM, 256, SMEM_SZ>>>(P1h, P1l, Wh + WOFF_W2, Wl + WOFF_W2,
                                 nullptr, 0, G, nullptr, nullptr, NN, 128);
    k_agg<<<GW, TE>>>(G, off, ssrc, sw, invd, b2, nullptr,
                      nullptr, P2h, P2l, 1);
    k_wmma<<<GM, 256, SMEM_SZ>>>(P2h, P2l, Wh + WOFF_W3, Wl + WOFF_W3,
                                 nullptr, 0, G, nullptr, nullptr, NN, 128);
    k_aggscore<<<GW, TE>>>(G, T, off + (NN + 1), ssrc + NE, sw + NE, invd + NN,
                           b3, out, 11);

    // ---- classifier GCN -> out cols 0..9 ----
    k_gemm10<<<GN, TE>>>(EAf, Wc, C10);
    k_agg10<<<GW, TE>>>(C10, off, ssrc, sw, invd, bc, out);
}